// round 17
// baseline (speedup 1.0000x reference)
#include <cuda_runtime.h>
#include <cuda_bf16.h>
#include <cuda_fp16.h>
#include <cstdint>
#include <cstddef>

#define DEV_INLINE __device__ __forceinline__

// ---------------- problem constants (fixed shapes) ----------------
constexpr int N_ROWS = 4096;
constexpr int DIM    = 512;
constexpr int NCLS   = 50000;
constexpr float S_SCALE    = 30.0f;
constexpr float EXP2C      = 43.280851226668905f;   // 30 * log2(e)
constexpr float MARGIN_COS = 0.9210609940028851f;   // cos(0.4)
constexpr float MARGIN_SIN = 0.3894183423086505f;   // sin(0.4)

// ---------------- GEMM tiling ----------------
constexpr int BM = 128;
constexpr int BN = 128;
constexpr int BK = 64;                 // 64 bf16 = 128B rows (SW128 atom)
constexpr int NKI = DIM / BK;          // 8 k-iterations
constexpr int NSTAGE = 3;
constexpr int MTILES = N_ROWS / BM;                  // 32
constexpr int NTILES = (NCLS + BN - 1) / BN;         // 391 (last masked)

constexpr uint32_t A_STAGE = BM * 128;               // 16384
constexpr uint32_t B_STAGE = BN * 128;               // 16384
constexpr uint32_t STAGE_BYTES = A_STAGE + B_STAGE;  // 32768
constexpr uint32_t SMEM_MBAR = NSTAGE * STAGE_BYTES;         // 98304
constexpr uint32_t SMEM_TOTAL = SMEM_MBAR + NSTAGE * 16;     // 98352 (x2 CTA)

// merged prep kernel block split
constexpr int WCONV_BLOCKS = (int)(((size_t)NCLS * DIM) / 2048);  // 12500
constexpr int PREP_BLOCKS  = N_ROWS / 8;                          // 512

// mbar layout: full[s] at SMEM_MBAR + s*16, empty[s] at +8
#define FULL_MB(s)  (sb + SMEM_MBAR + (s) * 16)
#define EMPTY_MB(s) (sb + SMEM_MBAR + (s) * 16 + 8)

// ---------------- device scratch (allocation-free rule) ----------------
__device__ __nv_bfloat16 g_xbf[(size_t)N_ROWS * DIM];   // EXP2C * normalized x, bf16
__device__ __nv_bfloat16 g_wbf[(size_t)NCLS * DIM];     // W, bf16 (51MB, mostly L2)
__device__ float g_excl[N_ROWS];    // FULL row exp-sum; target term subtracted in finalize
__device__ float g_tgt[N_ROWS];     // clamped fp32 target cosine (computed in prep)

// ---------------- helpers ----------------
DEV_INLINE uint32_t smem_u32(const void* p) { return (uint32_t)__cvta_generic_to_shared(p); }
DEV_INLINE uint32_t swz(uint32_t o) { return o ^ ((o >> 3) & 0x70); }

DEV_INLINE void cp16(uint32_t dst, const void* src) {
    asm volatile("cp.async.cg.shared.global [%0], [%1], 16;" :: "r"(dst), "l"(src));
}

DEV_INLINE void cp_arrive(uint32_t mbar) {
    asm volatile("cp.async.mbarrier.arrive.noinc.shared.b64 [%0];"
                 :: "r"(mbar) : "memory");
}

DEV_INLINE void mbar_arrive(uint32_t mbar) {
    asm volatile("mbarrier.arrive.shared.b64 _, [%0];" :: "r"(mbar) : "memory");
}

DEV_INLINE void mbar_wait(uint32_t mbar, uint32_t parity) {
    asm volatile(
        "{\n\t.reg .pred P1;\n\t"
        "WL_%=:\n\t"
        "mbarrier.try_wait.parity.acquire.cta.shared::cta.b64 P1, [%0], %1, 0x989680;\n\t"
        "@P1 bra.uni WD_%=;\n\t"
        "bra.uni WL_%=;\n\t"
        "WD_%=:\n\t}"
        :: "r"(mbar), "r"(parity) : "memory");
}

DEV_INLINE void ldm_x4(uint32_t& r0, uint32_t& r1, uint32_t& r2, uint32_t& r3,
                       uint32_t addr) {
    asm volatile("ldmatrix.sync.aligned.m8n8.x4.shared.b16 {%0,%1,%2,%3}, [%4];"
                 : "=r"(r0), "=r"(r1), "=r"(r2), "=r"(r3) : "r"(addr));
}

DEV_INLINE void mma_bf16(float* d, const uint32_t* a, uint32_t b0, uint32_t b1) {
    asm volatile(
        "mma.sync.aligned.m16n8k16.row.col.f32.bf16.bf16.f32 "
        "{%0,%1,%2,%3}, {%4,%5,%6,%7}, {%8,%9}, {%0,%1,%2,%3};"
        : "+f"(d[0]), "+f"(d[1]), "+f"(d[2]), "+f"(d[3])
        : "r"(a[0]), "r"(a[1]), "r"(a[2]), "r"(a[3]), "r"(b0), "r"(b1));
}

// paired exp2 on f16x2: input two PRE-SCALED accs (already EXP2C * logit)
DEV_INLINE float exp2_pair(float a0, float a1) {
    __half2 h = __float22half2_rn(make_float2(a0, a1));
    float2 e = __half22float2(h2exp2(h));
    return e.x + e.y;
}

// ---------------- kernel 1: merged prep ----------------
// blocks [0, WCONV_BLOCKS): W fp32 -> bf16 (8 floats/thread, 16B store)
// blocks [WCONV_BLOCKS, +PREP_BLOCKS): x normalize*EXP2C -> bf16, fp32 target
//                                      dot, zero g_excl (one warp per row)
__global__ void prep_kernel(const float* __restrict__ W,
                            const float* __restrict__ x,
                            const int* __restrict__ target) {
    if (blockIdx.x < WCONV_BLOCKS) {
        size_t i = ((size_t)blockIdx.x * blockDim.x + threadIdx.x) * 8;
        float4 a = *reinterpret_cast<const float4*>(W + i);
        float4 b = *reinterpret_cast<const float4*>(W + i + 4);
        __nv_bfloat162 p0 = __floats2bfloat162_rn(a.x, a.y);
        __nv_bfloat162 p1 = __floats2bfloat162_rn(a.z, a.w);
        __nv_bfloat162 p2 = __floats2bfloat162_rn(b.x, b.y);
        __nv_bfloat162 p3 = __floats2bfloat162_rn(b.z, b.w);
        uint4 o;
        o.x = *reinterpret_cast<uint32_t*>(&p0);
        o.y = *reinterpret_cast<uint32_t*>(&p1);
        o.z = *reinterpret_cast<uint32_t*>(&p2);
        o.w = *reinterpret_cast<uint32_t*>(&p3);
        *reinterpret_cast<uint4*>(g_wbf + i) = o;
        return;
    }

    int row = (blockIdx.x - WCONV_BLOCKS) * 8 + (threadIdx.x >> 5);
    int lid = threadIdx.x & 31;
    const float4* xr = reinterpret_cast<const float4*>(x + (size_t)row * DIM);
    int tg = __ldg(target + row);
    const float4* wr = reinterpret_cast<const float4*>(W + (size_t)tg * DIM);

    float4 xv[4];
    float ss = 0.0f, dp = 0.0f;
#pragma unroll
    for (int j = 0; j < 4; j++) {
        float4 v = xr[lid + j * 32];
        float4 w = wr[lid + j * 32];
        xv[j] = v;
        ss += v.x * v.x + v.y * v.y + v.z * v.z + v.w * v.w;
        dp += v.x * w.x + v.y * w.y + v.z * w.z + v.w * w.w;
    }
#pragma unroll
    for (int o = 16; o; o >>= 1) {
        ss += __shfl_xor_sync(0xFFFFFFFFu, ss, o);
        dp += __shfl_xor_sync(0xFFFFFFFFu, dp, o);
    }
    float rn  = rsqrtf(ss);
    float rnq = rn * EXP2C;   // fold exp2 scale into the A operand
    __nv_bfloat16* outr = g_xbf + (size_t)row * DIM;
#pragma unroll
    for (int j = 0; j < 4; j++) {
        float4 v = xv[j];
        __nv_bfloat162 p0 = __floats2bfloat162_rn(v.x * rnq, v.y * rnq);
        __nv_bfloat162 p1 = __floats2bfloat162_rn(v.z * rnq, v.w * rnq);
        uint32_t u0 = *reinterpret_cast<uint32_t*>(&p0);
        uint32_t u1 = *reinterpret_cast<uint32_t*>(&p1);
        *reinterpret_cast<uint2*>(outr + (lid + j * 32) * 4) = make_uint2(u0, u1);
    }
    if (lid == 0) {
        float t = dp * rn;
        g_tgt[row]  = fminf(fmaxf(t, -1.0f + 1e-7f), 1.0f - 1e-7f);
        g_excl[row] = 0.0f;   // re-zero on every graph replay
    }
}

// ---------------- kernel 2: HMMA GEMM + f16x2-exp2 epilogue ----------
// BM=128 x BN=128, 8 warps 2x4, 64x32 warp tiles, 2 CTAs/SM, 3-stage mbarrier
// pipeline. Accumulators hold EXP2C*logit (scale folded into A). Epilogue does
// one ex2.approx.f16x2 per element-pair; target term subtracted in finalize.
__global__ void __launch_bounds__(256, 2)
arc_gemm_kernel() {
    extern __shared__ char smem[];
    const uint32_t sb = smem_u32(smem);

    const int tid = threadIdx.x;
    const int lid = tid & 31;
    const int wid = tid >> 5;
    const int wm  = wid & 1;          // 0..1  (m, 64 rows each)
    const int wn  = wid >> 1;         // 0..3  (n, 32 cols each)
    const int rbase = blockIdx.x * BM;
    const int cbase = blockIdx.y * BN;

    if (tid == 0) {
#pragma unroll
        for (int s = 0; s < NSTAGE; s++) {
            asm volatile("mbarrier.init.shared.b64 [%0], 256;" :: "r"(FULL_MB(s))  : "memory");
            asm volatile("mbarrier.init.shared.b64 [%0], 256;" :: "r"(EMPTY_MB(s)) : "memory");
        }
    }
    __syncthreads();   // mbarrier init visible before any arrive/wait

    // ---- cp.async source pointers & swizzled dst offsets, hoisted ----
    const int c_row = tid >> 3;          // rows advance by 32 per i
    const int c_kb  = tid & 7;
    const __nv_bfloat16* xp[4];
    const __nv_bfloat16* wp[4];
    uint32_t dstoff[4];
#pragma unroll
    for (int i = 0; i < 4; i++) {
        int row = c_row + i * 32;
        xp[i] = g_xbf + (size_t)(rbase + row) * DIM + c_kb * 8;
        int c = cbase + row; c = (c < NCLS) ? c : (NCLS - 1);  // clamp hoisted
        wp[i] = g_wbf + (size_t)c * DIM + c_kb * 8;
        dstoff[i] = swz(row * 128 + c_kb * 16);
    }

    // ---- LDSM address decomposition: addr = base + rowoff + xk[kk] ----
    const uint32_t a_row  = wm * 64 + (lid & 15);
    const uint32_t a_koff = (lid >> 4) * 16;
    const uint32_t b_row  = wn * 32 + (lid & 7) + ((lid >> 4) & 1) * 8;
    const uint32_t b_koff = ((lid >> 3) & 1) * 16;
    const uint32_t maskA  = (a_row & 7) << 4;
    const uint32_t maskB  = (b_row & 7) << 4;
    uint32_t offA[4], offB[2], xka[4], xkb[4];
#pragma unroll
    for (int mt = 0; mt < 4; mt++) offA[mt] = (a_row + mt * 16) * 128;
#pragma unroll
    for (int np = 0; np < 2; np++) offB[np] = (b_row + np * 16) * 128;
#pragma unroll
    for (int kk = 0; kk < 4; kk++) {
        xka[kk] = (kk * 32 + a_koff) ^ maskA;
        xkb[kk] = (kk * 32 + b_koff) ^ maskB;
    }

    float acc[4][4][4];
#pragma unroll
    for (int mt = 0; mt < 4; mt++)
#pragma unroll
        for (int nt = 0; nt < 4; nt++)
#pragma unroll
            for (int j = 0; j < 4; j++) acc[mt][nt][j] = 0.0f;

    // ---- prologue: fill stages 0 and 1 (fresh, no empty wait) ----
#pragma unroll
    for (int pk = 0; pk < 2; pk++) {
        const int k0 = pk * BK;
        const uint32_t sa  = sb + pk * STAGE_BYTES;
        const uint32_t sbb = sa + A_STAGE;
#pragma unroll
        for (int i = 0; i < 4; i++) cp16(sa + dstoff[i], xp[i] + k0);
#pragma unroll
        for (int i = 0; i < 4; i++) cp16(sbb + dstoff[i], wp[i] + k0);
        cp_arrive(FULL_MB(pk));
    }

    uint32_t afr[4][4];
    uint32_t bfr[4][2];

    // ---- mainloop: fully unrolled; stage s=k%3, full parity (k/3)&1.
#pragma unroll
    for (int k = 0; k < NKI; k++) {
        const int s = k % 3;
        const uint32_t abase = sb + s * STAGE_BYTES;
        const uint32_t bbase = abase + A_STAGE;

        mbar_wait(FULL_MB(s), (k / 3) & 1);

        // kk=0 fragment loads first: crossbar starts immediately
        {
            const uint32_t ax = abase + xka[0];
            const uint32_t bx = bbase + xkb[0];
#pragma unroll
            for (int mt = 0; mt < 4; mt++)
                ldm_x4(afr[mt][0], afr[mt][1], afr[mt][2], afr[mt][3], ax + offA[mt]);
#pragma unroll
            for (int np = 0; np < 2; np++) {
                uint32_t r0, r1, r2, r3;
                ldm_x4(r0, r1, r2, r3, bx + offB[np]);
                bfr[np * 2][0] = r0;     bfr[np * 2][1] = r1;
                bfr[np * 2 + 1][0] = r2; bfr[np * 2 + 1][1] = r3;
            }
        }

        // produce stage k+2
        if (k + 2 < NKI) {
            const int s2 = (k + 2) % 3;
            const int fi = (k + 2) / 3;          // 0 => fresh (stage 2 only)
            if (k + 2 > 2) mbar_wait(EMPTY_MB(s2), (fi - 1) & 1);
            const int k0 = (k + 2) * BK;
            const uint32_t sa  = sb + s2 * STAGE_BYTES;
            const uint32_t sbb = sa + A_STAGE;
#pragma unroll
            for (int i = 0; i < 4; i++) cp16(sa + dstoff[i], xp[i] + k0);
#pragma unroll
            for (int i = 0; i < 4; i++) cp16(sbb + dstoff[i], wp[i] + k0);
            cp_arrive(FULL_MB(s2));
        }

        // kk loop: MMA(kk), then LDSM(kk+1)
#pragma unroll
        for (int kk = 0; kk < 4; kk++) {
#pragma unroll
            for (int mt = 0; mt < 4; mt++)
#pragma unroll
                for (int nt = 0; nt < 4; nt++)
                    mma_bf16(acc[mt][nt], afr[mt], bfr[nt][0], bfr[nt][1]);
            if (kk < 3) {
                const uint32_t ax = abase + xka[kk + 1];
                const uint32_t bx = bbase + xkb[kk + 1];
#pragma unroll
                for (int mt = 0; mt < 4; mt++)
                    ldm_x4(afr[mt][0], afr[mt][1], afr[mt][2], afr[mt][3],
                           ax + offA[mt]);
#pragma unroll
                for (int np = 0; np < 2; np++) {
                    uint32_t r0, r1, r2, r3;
                    ldm_x4(r0, r1, r2, r3, bx + offB[np]);
                    bfr[np * 2][0] = r0;     bfr[np * 2][1] = r1;
                    bfr[np * 2 + 1][0] = r2; bfr[np * 2 + 1][1] = r3;
                }
            }
        }

        // release stage for refill (only while fills remain)
        if (k + 3 < NKI) mbar_arrive(EMPTY_MB(s));
    }

    // ---- epilogue: paired f16x2 exp2 (acc already EXP2C-scaled), REDs ----
    // c-frag: d0=(r,c0) d1=(r,c0+1) d2=(r+8,c0) d3=(r+8,c0+1); r=lid>>2, c0=2*(lid&3)
    if (cbase + BN <= NCLS) {
        // fast path: all 128 columns valid (390 of 391 tiles)
#pragma unroll
        for (int mt = 0; mt < 4; mt++) {
#pragma unroll
            for (int h = 0; h < 2; h++) {
                int grow = rbase + wm * 64 + mt * 16 + (lid >> 2) + h * 8;
                float s = 0.0f;
#pragma unroll
                for (int nt = 0; nt < 4; nt++)
                    s += exp2_pair(acc[mt][nt][h * 2], acc[mt][nt][h * 2 + 1]);
                s += __shfl_xor_sync(0xFFFFFFFFu, s, 1);
                s += __shfl_xor_sync(0xFFFFFFFFu, s, 2);
                if ((lid & 3) == 0) atomicAdd(&g_excl[grow], s);
            }
        }
    } else {
        // tail tile: mask c >= NCLS (clamp-loaded duplicates), fp32 exp2
#pragma unroll
        for (int mt = 0; mt < 4; mt++) {
#pragma unroll
            for (int h = 0; h < 2; h++) {
                int grow = rbase + wm * 64 + mt * 16 + (lid >> 2) + h * 8;
                float s = 0.0f;
#pragma unroll
                for (int nt = 0; nt < 4; nt++) {
#pragma unroll
                    for (int j = 0; j < 2; j++) {
                        int c = cbase + wn * 32 + nt * 8 + 2 * (lid & 3) + j;
                        if (c < NCLS) s += exp2f(acc[mt][nt][h * 2 + j]);
                    }
                }
                s += __shfl_xor_sync(0xFFFFFFFFu, s, 1);
                s += __shfl_xor_sync(0xFFFFFFFFu, s, 2);
                if ((lid & 3) == 0) atomicAdd(&g_excl[grow], s);
            }
        }
    }
}

// ---------------- kernel 3: finalize — single block, writes output ----------
__global__ void finalize_kernel(float* __restrict__ out) {
    __shared__ float red[32];
    int tid = threadIdx.x;   // 1024 threads
    float s = 0.0f;
#pragma unroll
    for (int j = 0; j < N_ROWS / 1024; j++) {
        int i = tid + j * 1024;
        float t = g_tgt[i];   // already clamped fp32 cosine
        float num = S_SCALE * (t * MARGIN_COS
                               - sqrtf(fmaxf(1.0f - t * t, 0.0f)) * MARGIN_SIN);
        float excl = g_excl[i] - exp2f(EXP2C * t);   // subtract target term
        float den = expf(num) + excl;
        s += num - logf(den);
    }
#pragma unroll
    for (int o = 16; o; o >>= 1) s += __shfl_xor_sync(0xFFFFFFFFu, s, o);
    if ((tid & 31) == 0) red[tid >> 5] = s;
    __syncthreads();
    if (tid < 32) {
        float v = red[tid];
#pragma unroll
        for (int o = 16; o; o >>= 1) v += __shfl_xor_sync(0xFFFFFFFFu, v, o);
        if (tid == 0) out[0] = -v / (float)N_ROWS;
    }
}

// ---------------- launch ----------------
extern "C" void kernel_launch(void* const* d_in, const int* in_sizes, int n_in,
                              void* d_out, int out_size) {
    const float* x      = (const float*)d_in[0];
    const float* W      = (const float*)d_in[1];
    const int*   target = (const int*)d_in[2];
    float*       out    = (float*)d_out;

    cudaFuncSetAttribute(arc_gemm_kernel,
                         cudaFuncAttributeMaxDynamicSharedMemorySize, SMEM_TOTAL);

    prep_kernel<<<WCONV_BLOCKS + PREP_BLOCKS, 256>>>(W, x, target);
    arc_gemm_kernel<<<dim3(MTILES, NTILES), 256, SMEM_TOTAL>>>();
    finalize_kernel<<<1, 1024>>>(out);
}